// round 2
// baseline (speedup 1.0000x reference)
#include <cuda_runtime.h>
#include <math.h>

#define NB     32
#define NA     33600
#define K_TOP  1000
#define NBINS  8192
#define NSUB   2048
#define NCAND  2048

// smem layout for topk: sbits[NA] u32 | hist[NBINS] u32 | cand[NCAND] u64
#define SM_SBITS_B   (NA * 4)                    // 134400
#define SM_HIST_B    (NBINS * 4)                 // 32768
#define SM_CAND_B    (NCAND * 8)                 // 16384
#define SM_TOTAL_B   (SM_SBITS_B + SM_HIST_B + SM_CAND_B)   // 183552

// scratch (static device globals — no allocation)
__device__ float g_scores[NB * NA];   // 4.3 MB, stays L2-resident
__device__ int   g_keep[NB * K_TOP];

// Bitwise match of XLA GPU logistic: 1/(1+exp(-x)) with libdevice expf and
// IEEE div.rn (nvcc defaults, no fast-math). DO NOT refactor algebraically —
// output ordering must be bit-exact vs reference. (rel_err 5e-9 confirms.)
__device__ __forceinline__ float sigref(float x) {
    return 1.0f / (1.0f + expf(-x));
}

// ---------------------------------------------------------------------------
// Kernel 1: score[b, a] = sigmoid(cls) * sigmoid(obj), float4-vectorized.
// Level boundaries (25600, 32000) and NA are divisible by 4 -> no straddle.
// ---------------------------------------------------------------------------
__global__ void score_kernel(const float* __restrict__ cls0, const float* __restrict__ cls1,
                             const float* __restrict__ cls2,
                             const float* __restrict__ obj0, const float* __restrict__ obj1,
                             const float* __restrict__ obj2) {
    int i4 = blockIdx.x * blockDim.x + threadIdx.x;
    if (i4 >= NB * NA / 4) return;
    int b  = i4 / (NA / 4);
    int a4 = i4 - b * (NA / 4);
    const float4 *cp, *op;
    int p4;
    if (a4 < 6400)      { cp = (const float4*)cls0 + b * 6400; op = (const float4*)obj0 + b * 6400; p4 = a4; }
    else if (a4 < 8000) { cp = (const float4*)cls1 + b * 1600; op = (const float4*)obj1 + b * 1600; p4 = a4 - 6400; }
    else                { cp = (const float4*)cls2 + b * 400;  op = (const float4*)obj2 + b * 400;  p4 = a4 - 8000; }
    float4 c = cp[p4];
    float4 o = op[p4];
    float4 r;
    r.x = sigref(c.x) * sigref(o.x);
    r.y = sigref(c.y) * sigref(o.y);
    r.z = sigref(c.z) * sigref(o.z);
    r.w = sigref(c.w) * sigref(o.w);
    ((float4*)g_scores)[i4] = r;
}

// ---------------------------------------------------------------------------
// Kernel 2: exact sorted top-1000 per batch (one CTA per batch, 1024 threads)
// ---------------------------------------------------------------------------

// Find threshold bin: largest bin T with count(bins > T) < K <= count(bins >= T).
__device__ void find_thresh(unsigned int* hist, int nbins, int K, int tid,
                            int* wsum, int* s_bin, int* s_above) {
    int per  = nbins >> 10;
    int base = nbins - 1 - tid * per;
    int tsum = 0;
#pragma unroll 4
    for (int q = 0; q < per; q++) tsum += (int)hist[base - q];

    int lane = tid & 31, wid = tid >> 5;
    int x = tsum;
#pragma unroll
    for (int d = 1; d < 32; d <<= 1) {
        int n = __shfl_up_sync(0xffffffffu, x, d);
        if (lane >= d) x += n;
    }
    if (lane == 31) wsum[wid] = x;
    __syncthreads();
    if (wid == 0) {
        int w = wsum[lane];
#pragma unroll
        for (int d = 1; d < 32; d <<= 1) {
            int n = __shfl_up_sync(0xffffffffu, w, d);
            if (lane >= d) w += n;
        }
        wsum[lane] = w;
    }
    __syncthreads();
    int excl = (wid == 0 ? 0 : wsum[wid - 1]) + (x - tsum);

    if (excl < K && excl + tsum >= K) {     // exactly one thread
        int c = excl;
        for (int q = 0; q < per; q++) {
            int bin = base - q;
            int h = (int)hist[bin];
            if (c + h >= K) { *s_bin = bin; *s_above = c; break; }
            c += h;
        }
    }
    __syncthreads();
}

extern __shared__ unsigned char sm_raw[];

__global__ __launch_bounds__(1024) void topk_kernel(float* __restrict__ dout) {
    unsigned int*       sbits = (unsigned int*)sm_raw;                       // NA
    unsigned int*       hist  = (unsigned int*)(sm_raw + SM_SBITS_B);        // NBINS
    unsigned long long* cand  = (unsigned long long*)(sm_raw + SM_SBITS_B + SM_HIST_B); // NCAND
    __shared__ int  wsum[32];
    __shared__ int  s_bin, s_above;
    __shared__ unsigned int s_cnt;

    int b = blockIdx.x;
    int tid = threadIdx.x;

    // Phase 1: vectorized load from L2, cache bits in smem, coarse histogram
    // on bits >> 17 (scores in [0,1) -> bin < 8192).
    for (int q = tid; q < NBINS; q += 1024) hist[q] = 0u;
    __syncthreads();
    {
        const uint4* sv = (const uint4*)(g_scores + b * NA);
        uint4* dv = (uint4*)sbits;
        for (int q = tid; q < NA / 4; q += 1024) {
            uint4 v = sv[q];
            dv[q] = v;
            atomicAdd(&hist[v.x >> 17], 1u);
            atomicAdd(&hist[v.y >> 17], 1u);
            atomicAdd(&hist[v.z >> 17], 1u);
            atomicAdd(&hist[v.w >> 17], 1u);
        }
    }
    __syncthreads();
    find_thresh(hist, NBINS, K_TOP, tid, wsum, &s_bin, &s_above);
    int T = s_bin;
    int need2 = K_TOP - s_above;
    __syncthreads();

    // Phase 2: refine within bin T: 2048 sub-bins on bits[16:6] (smem reads)
    for (int q = tid; q < NSUB; q += 1024) hist[q] = 0u;
    __syncthreads();
    for (int a = tid; a < NA; a += 1024) {
        unsigned int bits = sbits[a];
        if ((int)(bits >> 17) == T) atomicAdd(&hist[(bits >> 6) & 2047u], 1u);
    }
    __syncthreads();
    find_thresh(hist, NSUB, need2, tid, wsum, &s_bin, &s_above);
    unsigned int cut = ((unsigned int)T << 17) | ((unsigned int)s_bin << 6);
    __syncthreads();

    // Phase 3: compact candidates (bits >= cut) as sortable 64-bit keys.
    // key = (bits << 32) | ~index : bigger key == better (score desc, index asc).
    if (tid == 0) s_cnt = 0u;
    __syncthreads();
    for (int a = tid; a < NA; a += 1024) {
        unsigned int bits = sbits[a];
        if (bits >= cut) {
            unsigned int pos = atomicAdd(&s_cnt, 1u);
            if (pos < NCAND)
                cand[pos] = ((unsigned long long)bits << 32) |
                            (unsigned long long)(0xFFFFFFFFu - (unsigned int)a);
        }
    }
    __syncthreads();
    int cnt = (int)s_cnt; if (cnt > NCAND) cnt = NCAND;

    // Phase 4: rank by counting (keys are unique -> ranks are a permutation).
    // Each thread owns candidates tid and tid+1024; inner loop is a smem
    // broadcast over all candidates. No barriers, no sort.
    unsigned long long k0 = (tid < cnt)        ? cand[tid]        : 0ull;
    unsigned long long k1 = (tid + 1024 < cnt) ? cand[tid + 1024] : 0ull;
    int r0 = 0, r1 = 0;
#pragma unroll 4
    for (int j = 0; j < cnt; j++) {
        unsigned long long kj = cand[j];
        r0 += (kj > k0);
        r1 += (kj > k1);
    }

    // Phase 5: emit kept indices + score column of dets
    if (tid < cnt && r0 < K_TOP) {
        unsigned int bits = (unsigned int)(k0 >> 32);
        unsigned int a    = 0xFFFFFFFFu - (unsigned int)(k0 & 0xFFFFFFFFull);
        g_keep[b * K_TOP + r0] = (int)a;
        dout[b * (K_TOP * 5) + r0 * 5 + 4] = __uint_as_float(bits);
    }
    if (tid + 1024 < cnt && r1 < K_TOP) {
        unsigned int bits = (unsigned int)(k1 >> 32);
        unsigned int a    = 0xFFFFFFFFu - (unsigned int)(k1 & 0xFFFFFFFFull);
        g_keep[b * K_TOP + r1] = (int)a;
        dout[b * (K_TOP * 5) + r1 * 5 + 4] = __uint_as_float(bits);
    }
}

// ---------------------------------------------------------------------------
// Kernel 3: decode kept anchors. 18 tasks per detection: 17 kpts + 1 bbox.
// ---------------------------------------------------------------------------
__global__ void decode_kernel(const float* __restrict__ bbox0, const float* __restrict__ bbox1,
                              const float* __restrict__ bbox2,
                              const float* __restrict__ kpt0,  const float* __restrict__ kpt1,
                              const float* __restrict__ kpt2,
                              const float* __restrict__ vis0,  const float* __restrict__ vis1,
                              const float* __restrict__ vis2,
                              float* __restrict__ dout) {
    const int NTASK = NB * K_TOP * 18;
    int task = blockIdx.x * blockDim.x + threadIdx.x;
    if (task >= NTASK) return;
    int det = task / 18;
    int sub = task - det * 18;
    int b   = det / K_TOP;
    int a   = g_keep[det];

    int p, HW, l;
    float s, px, py;
    if (a < 25600)      { p = a;         HW = 25600; s = 8.0f;  l = 0; px = (float)(p % 160) * 8.0f;  py = (float)(p / 160) * 8.0f;  }
    else if (a < 32000) { p = a - 25600; HW = 6400;  s = 16.0f; l = 1; px = (float)(p % 80)  * 16.0f; py = (float)(p / 80)  * 16.0f; }
    else                { p = a - 32000; HW = 1600;  s = 32.0f; l = 2; px = (float)(p % 40)  * 32.0f; py = (float)(p / 40)  * 32.0f; }

    if (sub < 17) {
        int k = sub;
        const float* kp = (l == 0) ? kpt0 : (l == 1) ? kpt1 : kpt2;
        const float* vp = (l == 0) ? vis0 : (l == 1) ? vis1 : vis2;
        float kx = kp[(b * 34 + 2 * k)     * HW + p];
        float ky = kp[(b * 34 + 2 * k + 1) * HW + p];
        float v  = vp[(b * 17 + k)         * HW + p];
        int off = NB * K_TOP * 5 + det * 51 + k * 3;
        dout[off + 0] = kx * s + px;
        dout[off + 1] = ky * s + py;
        dout[off + 2] = sigref(v);
    } else {
        const float* bp = (l == 0) ? bbox0 : (l == 1) ? bbox1 : bbox2;
        float bx = bp[(b * 4 + 0) * HW + p];
        float by = bp[(b * 4 + 1) * HW + p];
        float bw = bp[(b * 4 + 2) * HW + p];
        float bh = bp[(b * 4 + 3) * HW + p];
        float x  = bx * s + px;
        float y  = by * s + py;
        float hw = expf(bw) * s * 0.5f;
        float hh = expf(bh) * s * 0.5f;
        int off = det * 5;
        dout[off + 0] = x - hw;
        dout[off + 1] = y - hh;
        dout[off + 2] = x + hw;
        dout[off + 3] = y + hh;
    }
}

// ---------------------------------------------------------------------------
extern "C" void kernel_launch(void* const* d_in, const int* in_sizes, int n_in,
                              void* d_out, int out_size) {
    const float* cls0  = (const float*)d_in[0];
    const float* cls1  = (const float*)d_in[1];
    const float* cls2  = (const float*)d_in[2];
    const float* bbox0 = (const float*)d_in[3];
    const float* bbox1 = (const float*)d_in[4];
    const float* bbox2 = (const float*)d_in[5];
    const float* obj0  = (const float*)d_in[6];
    const float* obj1  = (const float*)d_in[7];
    const float* obj2  = (const float*)d_in[8];
    const float* kpt0  = (const float*)d_in[9];
    const float* kpt1  = (const float*)d_in[10];
    const float* kpt2  = (const float*)d_in[11];
    const float* vis0  = (const float*)d_in[12];
    const float* vis1  = (const float*)d_in[13];
    const float* vis2  = (const float*)d_in[14];
    float* dout = (float*)d_out;

    cudaFuncSetAttribute(topk_kernel, cudaFuncAttributeMaxDynamicSharedMemorySize,
                         SM_TOTAL_B);

    score_kernel<<<(NB * NA / 4 + 255) / 256, 256>>>(cls0, cls1, cls2, obj0, obj1, obj2);
    topk_kernel<<<NB, 1024, SM_TOTAL_B>>>(dout);
    decode_kernel<<<(NB * K_TOP * 18 + 255) / 256, 256>>>(bbox0, bbox1, bbox2,
                                                          kpt0, kpt1, kpt2,
                                                          vis0, vis1, vis2, dout);
}